// round 15
// baseline (speedup 1.0000x reference)
#include <cuda_runtime.h>
#include <cuda_fp16.h>
#include <cstdint>
#include <math_constants.h>

// ============================ problem shapes ============================
#define BATCH 8
#define SEQ   2048
#define DQ    512
#define DKV   768
#define HDIM  512
#define MROWS (BATCH*SEQ)   // 16384

// ============================ device scratch ============================
__device__ __half g_Xh[(size_t)MROWS*DQ],  g_Xl[(size_t)MROWS*DQ];
__device__ __half g_KVh[(size_t)MROWS*DKV], g_KVl[(size_t)MROWS*DKV];
__device__ __half g_Wqh[HDIM*DQ],  g_Wql[HDIM*DQ];
__device__ __half g_Wkh[HDIM*DKV], g_Wkl[HDIM*DKV];
__device__ __half g_Wvh[DQ*DKV];
__device__ float  g_F [(size_t)MROWS*HDIM];
__device__ float  g_F2[(size_t)MROWS*HDIM];
__device__ float  g_F3[(size_t)MROWS*DQ];
__device__ __half g_Qh[(size_t)MROWS*HDIM], g_Ql[(size_t)MROWS*HDIM];
__device__ __half g_Kh[(size_t)MROWS*HDIM], g_Kl[(size_t)MROWS*HDIM];
__device__ __half g_Vth[(size_t)BATCH*DQ*SEQ];
__device__ float  g_S[(size_t)BATCH*SEQ*SEQ];
__device__ __half g_Ph[(size_t)BATCH*SEQ*SEQ];

// ============================ GEMM config ============================
// CTA tile 128x128, K-tile 32 fp16, 256 threads (8 warps: 2m x 4n, 64x32 each).
// Tile: 128 rows x 64 B, XOR-swizzled (chunk ^= (row>>1)&3).
#define TILE_B   8192

__device__ __forceinline__ uint32_t smem_u32(const void* p) {
    uint32_t a;
    asm("{ .reg .u64 t; cvta.to.shared.u64 t, %1; cvt.u32.u64 %0, t; }" : "=r"(a) : "l"(p));
    return a;
}
__device__ __forceinline__ void cp16(uint32_t sa, const void* ga) {
    asm volatile("cp.async.cg.shared.global [%0], [%1], 16;\n" :: "r"(sa), "l"(ga));
}
__device__ __forceinline__ void ldsm_x4(uint32_t* r, uint32_t addr) {
    asm volatile("ldmatrix.sync.aligned.m8n8.x4.shared.b16 {%0,%1,%2,%3}, [%4];"
                 : "=r"(r[0]), "=r"(r[1]), "=r"(r[2]), "=r"(r[3]) : "r"(addr));
}
// fp32 accumulate (main pass)
__device__ __forceinline__ void mma_f16(float* c,
                                        const uint32_t* a, uint32_t b0, uint32_t b1) {
    asm volatile(
        "mma.sync.aligned.m16n8k16.row.col.f32.f16.f16.f32 "
        "{%0,%1,%2,%3}, {%4,%5,%6,%7}, {%8,%9}, {%0,%1,%2,%3};\n"
        : "+f"(c[0]), "+f"(c[1]), "+f"(c[2]), "+f"(c[3])
        : "r"(a[0]), "r"(a[1]), "r"(a[2]), "r"(a[3]), "r"(b0), "r"(b1));
}
// fp16 accumulate (correction passes; values ~1e-2, fp16 exact enough)
__device__ __forceinline__ void mma_h(uint32_t* c,
                                      const uint32_t* a, uint32_t b0, uint32_t b1) {
    asm volatile(
        "mma.sync.aligned.m16n8k16.row.col.f16.f16.f16.f16 "
        "{%0,%1}, {%2,%3,%4,%5}, {%6,%7}, {%0,%1};\n"
        : "+r"(c[0]), "+r"(c[1])
        : "r"(a[0]), "r"(a[1]), "r"(a[2]), "r"(a[3]), "r"(b0), "r"(b1));
}

// Shared GEMM body, 256 threads, warp tile 64x32.
// NPASS=3: main = Ah*Bh (fp32 acc); corr = Ah*Bl + Al*Bh (fp16 acc), added at epilogue.
// NPASS=1: main only.
template<int NPASS, int NST>
__device__ __forceinline__ void gemm_body(
    const __half* __restrict__ Ah, const __half* __restrict__ Al, int lda, size_t aRow0,
    const __half* __restrict__ Bh, const __half* __restrict__ Bl, int ldb, size_t bRow0,
    float* __restrict__ C, int ldc, size_t cRow0, int n0,
    const float* __restrict__ bias, const float* __restrict__ Res,
    int Ktot, int epi, char* smem)
{
    constexpr int NTILE   = (NPASS == 3) ? 4 : 2;
    constexpr int STAGE_B = NTILE * TILE_B;
    constexpr uint32_t BOFF = (NPASS == 3) ? 2u * TILE_B : (uint32_t)TILE_B;
    constexpr int BH_TILE = (NPASS == 3) ? 2 : 1;

    const uint32_t sb = smem_u32(smem);
    const int tid  = threadIdx.x;
    const int wid  = tid >> 5;       // 0..7
    const int lane = tid & 31;
    const int g    = lane >> 2;
    const int t4   = lane & 3;
    const int wm   = wid & 1;        // 2 m-warps (64 rows)
    const int wn   = wid >> 1;       // 4 n-warps (32 cols)

    const int laneRow = (lane & 7) + ((lane >> 3) & 1) * 8;
    const int hi      = (lane >> 4) & 1;
    const int sw      = (laneRow >> 1) & 3;
    const uint32_t cb0 = (uint32_t)((hi ^ sw) * 16);
    const uint32_t cb1 = (uint32_t)(((2 + hi) ^ sw) * 16);

    float acc[4][4][4];
    uint32_t corr[4][4][2];
#pragma unroll
    for (int mt = 0; mt < 4; mt++)
#pragma unroll
        for (int nt = 0; nt < 4; nt++) {
#pragma unroll
            for (int r = 0; r < 4; r++) acc[mt][nt][r] = 0.f;
            corr[mt][nt][0] = 0u; corr[mt][nt][1] = 0u;
        }

    const int nkb = Ktot >> 5;

    auto load_stage = [&](uint32_t st, int k0) {
#pragma unroll
        for (int j = 0; j < NTILE * 2; j++) {
            const int i = tid + j * 256;
            const int tile = i >> 9;
            const int r = (i >> 2) & 127;
            const int c = i & 3;
            const __half* gp;
            if (tile == 0)                        gp = Ah + (aRow0 + r) * (size_t)lda + k0 + c * 8;
            else if (NPASS == 3 && tile == 1)     gp = Al + (aRow0 + r) * (size_t)lda + k0 + c * 8;
            else if (tile == BH_TILE)             gp = Bh + (bRow0 + r) * (size_t)ldb + k0 + c * 8;
            else                                  gp = Bl + (bRow0 + r) * (size_t)ldb + k0 + c * 8;
            const uint32_t sa = st + tile * TILE_B + r * 64 +
                                ((uint32_t)(c ^ ((r >> 1) & 3)) << 4);
            cp16(sa, gp);
        }
    };

#pragma unroll
    for (int p = 0; p < NST - 1; p++) {
        if (p < nkb) load_stage(sb + p * STAGE_B, p << 5);
        asm volatile("cp.async.commit_group;\n" ::: "memory");
    }

    const uint32_t aRowB = (uint32_t)((wm * 64 + laneRow) * 64);
    const uint32_t bRowB = (uint32_t)((wn * 32 + laneRow) * 64);

    int s = 0, spN = NST - 1;
    for (int kb = 0; kb < nkb; kb++) {
        asm volatile("cp.async.wait_group %0;\n" :: "n"(NST - 2) : "memory");
        __syncthreads();
        if (kb + NST - 1 < nkb)
            load_stage(sb + spN * STAGE_B, (kb + NST - 1) << 5);
        asm volatile("cp.async.commit_group;\n" ::: "memory");

        const uint32_t st = sb + s * STAGE_B;
        const uint32_t aBase = st + aRowB;
        const uint32_t bBase = st + BOFF + bRowB;

#pragma unroll
        for (int ks = 0; ks < 2; ks++) {
            const uint32_t cb = ks ? cb1 : cb0;
            uint32_t bh[2][4];
#pragma unroll
            for (int nb = 0; nb < 2; nb++)
                ldsm_x4(bh[nb], bBase + nb * 1024 + cb);
            uint32_t bl[2][4];
            if (NPASS == 3) {
#pragma unroll
                for (int nb = 0; nb < 2; nb++)
                    ldsm_x4(bl[nb], bBase + TILE_B + nb * 1024 + cb);
            }
#pragma unroll
            for (int mt = 0; mt < 4; mt++) {
                uint32_t ah[4], al[4];
                ldsm_x4(ah, aBase + mt * 1024 + cb);
                if (NPASS == 3)
                    ldsm_x4(al, aBase + TILE_B + mt * 1024 + cb);
#pragma unroll
                for (int nt = 0; nt < 4; nt++) {
                    const uint32_t b0 = bh[nt >> 1][nt & 1];
                    const uint32_t b1 = bh[nt >> 1][2 + (nt & 1)];
                    mma_f16(acc[mt][nt], ah, b0, b1);
                    if (NPASS == 3) {
                        mma_h(corr[mt][nt], ah,
                              bl[nt >> 1][nt & 1], bl[nt >> 1][2 + (nt & 1)]);
                        mma_h(corr[mt][nt], al, b0, b1);
                    }
                }
            }
        }
        if (++s == NST) s = 0;
        if (++spN == NST) spN = 0;
    }

    // epilogue: main + corr, fused bias / residual
    const int nw0 = n0 + wn * 32;
#pragma unroll
    for (int mt = 0; mt < 4; mt++) {
#pragma unroll
        for (int nt = 0; nt < 4; nt++) {
            const int m = wm * 64 + mt * 16 + g;
            const int n = nw0 + nt * 8 + t4 * 2;
            float v0 = acc[mt][nt][0], v1 = acc[mt][nt][1];
            float v2 = acc[mt][nt][2], v3 = acc[mt][nt][3];
            if (NPASS == 3) {
                const __half2 c0 = *(const __half2*)&corr[mt][nt][0];
                const __half2 c1 = *(const __half2*)&corr[mt][nt][1];
                v0 += __low2float(c0); v1 += __high2float(c0);
                v2 += __low2float(c1); v3 += __high2float(c1);
            }
            const size_t i0 = (cRow0 + m) * (size_t)ldc + n;
            const size_t i1 = (cRow0 + m + 8) * (size_t)ldc + n;
            if (epi == 1) {
                const float b0 = bias[n], b1 = bias[n + 1];
                v0 += b0; v1 += b1; v2 += b0; v3 += b1;
            } else if (epi == 2) {
                const float2 r0 = *(const float2*)(Res + i0);
                const float2 r1 = *(const float2*)(Res + i1);
                v0 += r0.x; v1 += r0.y; v2 += r1.x; v3 += r1.y;
            }
            float2 o0; o0.x = v0; o0.y = v1;
            float2 o1; o1.x = v2; o1.y = v3;
            *(float2*)(C + i0) = o0;
            *(float2*)(C + i1) = o1;
        }
    }
}

// 3-pass batched GEMM (scores): 1 CTA/SM, 4 stages
__global__ void __launch_bounds__(256, 1) gemm_mma3(
    const __half* __restrict__ Ah, const __half* __restrict__ Al, int lda, int aBatch,
    const __half* __restrict__ Bh, const __half* __restrict__ Bl, int ldb, int bBatch,
    float* __restrict__ C, int ldc, int cBatch, int Ktot)
{
    extern __shared__ char smem[];
    const size_t aRow0 = (size_t)blockIdx.z * aBatch + (size_t)blockIdx.y * 128;
    const size_t bRow0 = (size_t)blockIdx.z * bBatch + (size_t)blockIdx.x * 128;
    const size_t cRow0 = (size_t)blockIdx.z * cBatch + (size_t)blockIdx.y * 128;
    gemm_body<3, 4>(Ah, Al, lda, aRow0, Bh, Bl, ldb, bRow0,
                    C, ldc, cRow0, blockIdx.x * 128, nullptr, nullptr, Ktot, 0, smem);
}

// 1-pass batched GEMM (PV): 2 CTAs/SM, 3 stages
__global__ void __launch_bounds__(256, 2) gemm_mma1(
    const __half* __restrict__ Ah, int lda, int aBatch,
    const __half* __restrict__ Bh, int ldb, int bBatch,
    float* __restrict__ C, int ldc, int cBatch,
    const float* __restrict__ Res, int Ktot)
{
    extern __shared__ char smem[];
    const size_t aRow0 = (size_t)blockIdx.z * aBatch + (size_t)blockIdx.y * 128;
    const size_t bRow0 = (size_t)blockIdx.z * bBatch + (size_t)blockIdx.x * 128;
    const size_t cRow0 = (size_t)blockIdx.z * cBatch + (size_t)blockIdx.y * 128;
    gemm_body<1, 3>(Ah, nullptr, lda, aRow0, Bh, nullptr, ldb, bRow0,
                    C, ldc, cRow0, blockIdx.x * 128, nullptr, Res, Ktot, 2, smem);
}

// Fused Q/K/V projection: grid (4, 384)
__global__ void __launch_bounds__(256, 1) gemm_qkv(
    const __half* __restrict__ Xh, const __half* __restrict__ Xl,
    const __half* __restrict__ KVh, const __half* __restrict__ KVl,
    const __half* __restrict__ Wqh, const __half* __restrict__ Wql,
    const __half* __restrict__ Wkh, const __half* __restrict__ Wkl,
    const __half* __restrict__ Wvh,
    const float* __restrict__ bq, const float* __restrict__ bk, const float* __restrict__ bv,
    float* __restrict__ F, float* __restrict__ F2, float* __restrict__ F3)
{
    extern __shared__ char smem[];
    const int part = blockIdx.y >> 7;
    const size_t row0 = (size_t)(blockIdx.y & 127) * 128;
    const size_t bRow0 = (size_t)blockIdx.x * 128;
    const int n0 = blockIdx.x * 128;
    if (part == 0) {
        gemm_body<3, 4>(Xh, Xl, DQ, row0, Wqh, Wql, DQ, bRow0,
                        F, HDIM, row0, n0, bq, nullptr, DQ, 1, smem);
    } else if (part == 1) {
        gemm_body<3, 4>(KVh, KVl, DKV, row0, Wkh, Wkl, DKV, bRow0,
                        F2, HDIM, row0, n0, bk, nullptr, DKV, 1, smem);
    } else {
        gemm_body<1, 3>(KVh, nullptr, DKV, row0, Wvh, nullptr, DKV, bRow0,
                        F3, DQ, row0, n0, bv, nullptr, DKV, 1, smem);
    }
}

// ======================= elementwise / helper kernels =======================
__device__ __forceinline__ void split_h(float x, __half& h, __half& l) {
    h = __float2half_rn(x);
    l = __float2half_rn(x - __half2float(h));
}

__global__ __launch_bounds__(256) void convert_hilo2(
    const float4* __restrict__ inq, __half2* __restrict__ hq, __half2* __restrict__ lq, int n4q,
    const float4* __restrict__ inkv, __half2* __restrict__ hkv, __half2* __restrict__ lkv, int n4kv)
{
    int i = blockIdx.x * 256 + threadIdx.x;
    const float4* in; __half2 *hi, *lo;
    if (i < n4q) { in = inq; hi = hq; lo = lq; }
    else {
        i -= n4q;
        if (i >= n4kv) return;
        in = inkv; hi = hkv; lo = lkv;
    }
    float4 v = in[i];
    __half h0, l0, h1, l1, h2, l2, h3, l3;
    split_h(v.x, h0, l0); split_h(v.y, h1, l1);
    split_h(v.z, h2, l2); split_h(v.w, h3, l3);
    hi[2 * i]     = __halves2half2(h0, h1);
    hi[2 * i + 1] = __halves2half2(h2, h3);
    lo[2 * i]     = __halves2half2(l0, l1);
    lo[2 * i + 1] = __halves2half2(l2, l3);
}

__device__ __forceinline__ void transpose_core(
    const float* __restrict__ in, int ldin,
    __half* __restrict__ oh, __half* __restrict__ ol, int ldout,
    int r0, int c0)
{
    __shared__ float t[32][33];
#pragma unroll
    for (int j = 0; j < 32; j += 8)
        t[threadIdx.y + j][threadIdx.x] =
            in[(size_t)(r0 + threadIdx.y + j) * ldin + c0 + threadIdx.x];
    __syncthreads();
#pragma unroll
    for (int j = 0; j < 32; j += 8) {
        float v = t[threadIdx.x][threadIdx.y + j];
        size_t oidx = (size_t)(c0 + threadIdx.y + j) * ldout + r0 + threadIdx.x;
        if (ol) {
            __half h, l; split_h(v, h, l);
            oh[oidx] = h; ol[oidx] = l;
        } else {
            oh[oidx] = __float2half_rn(v);
        }
    }
}

__global__ void transpose_w(
    const float* __restrict__ Wq, __half* __restrict__ Wqh, __half* __restrict__ Wql,
    const float* __restrict__ Wk, __half* __restrict__ Wkh, __half* __restrict__ Wkl,
    const float* __restrict__ Wv, __half* __restrict__ Wvh)
{
    const int z = blockIdx.z;
    if (z == 0) {
        if (blockIdx.x >= 16) return;
        transpose_core(Wq, HDIM, Wqh, Wql, DQ, blockIdx.x * 32, blockIdx.y * 32);
    } else if (z == 1) {
        transpose_core(Wk, HDIM, Wkh, Wkl, DKV, blockIdx.x * 32, blockIdx.y * 32);
    } else {
        transpose_core(Wv, DQ, Wvh, nullptr, DKV, blockIdx.x * 32, blockIdx.y * 32);
    }
}

__global__ void transpose_v(
    const float* __restrict__ in, __half* __restrict__ oh)
{
    const float* ip = in + (size_t)blockIdx.z * SEQ * DQ;
    __half* op = oh + (size_t)blockIdx.z * DQ * SEQ;
    transpose_core(ip, DQ, op, nullptr, SEQ, blockIdx.x * 32, blockIdx.y * 32);
}

__device__ __forceinline__ void ln_core(
    float* __restrict__ row, const float* __restrict__ gam, const float* __restrict__ bet,
    __half* __restrict__ oh, __half* __restrict__ ol, size_t obase)
{
    const int tid = threadIdx.x;
    float v0 = row[tid], v1 = row[tid + 256];
    __shared__ float sred[8];
    float s = v0 + v1;
#pragma unroll
    for (int o = 16; o; o >>= 1) s += __shfl_xor_sync(0xffffffffu, s, o);
    if ((tid & 31) == 0) sred[tid >> 5] = s;
    __syncthreads();
    float tot = 0.f;
#pragma unroll
    for (int i = 0; i < 8; i++) tot += sred[i];
    const float mean = tot * (1.0f / 512.0f);
    const float d0 = v0 - mean, d1 = v1 - mean;
    float q = d0 * d0 + d1 * d1;
#pragma unroll
    for (int o = 16; o; o >>= 1) q += __shfl_xor_sync(0xffffffffu, q, o);
    __syncthreads();
    if ((tid & 31) == 0) sred[tid >> 5] = q;
    __syncthreads();
    float qt = 0.f;
#pragma unroll
    for (int i = 0; i < 8; i++) qt += sred[i];
    const float rstd = rsqrtf(qt * (1.0f / 512.0f) + 1e-5f);
    float r0 = d0 * rstd * gam[tid] + bet[tid];
    float r1 = d1 * rstd * gam[tid + 256] + bet[tid + 256];
    if (oh) {
        __half h, l;
        split_h(r0, h, l); oh[obase + tid] = h;       ol[obase + tid] = l;
        split_h(r1, h, l); oh[obase + tid + 256] = h; ol[obase + tid + 256] = l;
    } else {
        row[tid] = r0; row[tid + 256] = r1;
    }
}

__global__ __launch_bounds__(256) void ln_qkv(
    float* __restrict__ F,  const float* __restrict__ gq, const float* __restrict__ betaq,
    __half* __restrict__ Qh, __half* __restrict__ Ql,
    float* __restrict__ F2, const float* __restrict__ gk, const float* __restrict__ betak,
    __half* __restrict__ Kh, __half* __restrict__ Kl,
    float* __restrict__ F3, const float* __restrict__ gv, const float* __restrict__ betav)
{
    const int b = blockIdx.x;
    if (b < MROWS) {
        ln_core(F + (size_t)b * 512, gq, betaq, Qh, Ql, (size_t)b * 512);
    } else if (b < 2 * MROWS) {
        const int r = b - MROWS;
        ln_core(F2 + (size_t)r * 512, gk, betak, Kh, Kl, (size_t)r * 512);
    } else {
        const int r = b - 2 * MROWS;
        ln_core(F3 + (size_t)r * 512, gv, betav, nullptr, nullptr, 0);
    }
}

__global__ __launch_bounds__(256) void softmax_convert(
    const float* __restrict__ S, __half* __restrict__ Ph)
{
    const float* row = S + (size_t)blockIdx.x * 2048;
    const int tid = threadIdx.x;
    __shared__ float sred[8];
    float vals[8];
    float lmax = -CUDART_INF_F;
#pragma unroll
    for (int i = 0; i < 8; i++) {
        vals[i] = row[tid + i * 256];
        lmax = fmaxf(lmax, vals[i]);
    }
#pragma unroll
    for (int o = 16; o; o >>= 1) lmax = fmaxf(lmax, __shfl_xor_sync(0xffffffffu, lmax, o));
    if ((tid & 31) == 0) sred[tid >> 5] = lmax;
    __syncthreads();
    float m = sred[0];
#pragma unroll
    for (int i = 1; i < 8; i++) m = fmaxf(m, sred[i]);
    float lsum = 0.f;
#pragma unroll
    for (int i = 0; i < 8; i++) { vals[i] = __expf(vals[i] - m); lsum += vals[i]; }
#pragma unroll
    for (int o = 16; o; o >>= 1) lsum += __shfl_xor_sync(0xffffffffu, lsum, o);
    __syncthreads();
    if ((tid & 31) == 0) sred[tid >> 5] = lsum;
    __syncthreads();
    float tot = 0.f;
#pragma unroll
    for (int i = 0; i < 8; i++) tot += sred[i];
    const float inv = 1.0f / tot;
    const size_t base = (size_t)blockIdx.x * 2048;
#pragma unroll
    for (int i = 0; i < 8; i++)
        Ph[base + tid + i * 256] = __float2half_rn(vals[i] * inv);
}

// ============================ launch ============================
extern "C" void kernel_launch(void* const* d_in, const int* in_sizes, int n_in,
                              void* d_out, int out_size)
{
    const float* q_seq = (const float*)d_in[0];
    const float* kv    = (const float*)d_in[1];
    const float* Wq    = (const float*)d_in[2];
    const float* bq    = (const float*)d_in[3];
    const float* gq    = (const float*)d_in[4];
    const float* betaq = (const float*)d_in[5];
    const float* Wk    = (const float*)d_in[6];
    const float* bk    = (const float*)d_in[7];
    const float* gk    = (const float*)d_in[8];
    const float* betak = (const float*)d_in[9];
    const float* Wv    = (const float*)d_in[10];
    const float* bv    = (const float*)d_in[11];
    const float* gv    = (const float*)d_in[12];
    const float* betav = (const float*)d_in[13];
    float* out = (float*)d_out;

    __half *Xh, *Xl, *KVh, *KVl, *Wqh, *Wql, *Wkh, *Wkl, *Wvh;
    __half *Qh, *Ql, *Kh, *Kl, *Vth, *Ph;
    float *F, *F2, *F3, *S;
    cudaGetSymbolAddress((void**)&Xh, g_Xh);   cudaGetSymbolAddress((void**)&Xl, g_Xl);
    cudaGetSymbolAddress((void**)&KVh, g_KVh); cudaGetSymbolAddress((void**)&KVl, g_KVl);
    cudaGetSymbolAddress((void**)&Wqh, g_Wqh); cudaGetSymbolAddress((void**)&Wql, g_Wql);
    cudaGetSymbolAddress((void**)&Wkh, g_Wkh); cudaGetSymbolAddress((void**)&Wkl, g_Wkl);
    cudaGetSymbolAddress((void**)&Wvh, g_Wvh);
    cudaGetSymbolAddress((void**)&Qh, g_Qh);   cudaGetSymbolAddress((void**)&Ql, g_Ql);
    cudaGetSymbolAddress((void**)&Kh, g_Kh);   cudaGetSymbolAddress((void**)&Kl, g_Kl);
    cudaGetSymbolAddress((void**)&Vth, g_Vth);
    cudaGetSymbolAddress((void**)&Ph, g_Ph);
    cudaGetSymbolAddress((void**)&F, g_F);     cudaGetSymbolAddress((void**)&F2, g_F2);
    cudaGetSymbolAddress((void**)&F3, g_F3);   cudaGetSymbolAddress((void**)&S, g_S);

    const int SMEM3 = 4 * 4 * TILE_B;   // 131072 (4 stages x 4 tiles) -> 1 CTA/SM
    const int SMEM1 = 3 * 2 * TILE_B;   // 49152  (3 stages x 2 tiles) -> 2 CTAs/SM
    cudaFuncSetAttribute((const void*)gemm_qkv,  cudaFuncAttributeMaxDynamicSharedMemorySize, SMEM3);
    cudaFuncSetAttribute((const void*)gemm_mma3, cudaFuncAttributeMaxDynamicSharedMemorySize, SMEM3);
    cudaFuncSetAttribute((const void*)gemm_mma1, cudaFuncAttributeMaxDynamicSharedMemorySize, SMEM1);

    const dim3 tb(32, 8);
    const int n4q = MROWS * DQ / 4, n4kv = MROWS * DKV / 4;

    // 0) split both inputs into fp16 hi/lo
    convert_hilo2<<<(n4q + n4kv + 255) / 256, 256>>>(
        (const float4*)q_seq, (__half2*)Xh, (__half2*)Xl, n4q,
        (const float4*)kv, (__half2*)KVh, (__half2*)KVl, n4kv);

    // 1) transpose all weights
    transpose_w<<<dim3(24, 16, 3), tb>>>(Wq, Wqh, Wql, Wk, Wkh, Wkl, Wv, Wvh);

    // 2) fused Q/K/V projections
    gemm_qkv<<<dim3(4, 384, 1), 256, SMEM3>>>(
        Xh, Xl, KVh, KVl, Wqh, Wql, Wkh, Wkl, Wvh, bq, bk, bv, F, F2, F3);

    // 3) fused LayerNorms
    ln_qkv<<<3 * MROWS, 256>>>(F, gq, betaq, Qh, Ql,
                               F2, gk, betak, Kh, Kl,
                               F3, gv, betav);

    // 4) transpose V -> Vt hi [b*512+c, 2048]
    transpose_v<<<dim3(SEQ / 32, DQ / 32, BATCH), tb>>>(F3, Vth);

    // 5) scores S = K . Q^T  (3-pass, fp16-acc corrections)
    gemm_mma3<<<dim3(SEQ / 128, SEQ / 128, BATCH), 256, SMEM3>>>(
        Kh, Kl, HDIM, SEQ, Qh, Ql, HDIM, SEQ, S, SEQ, SEQ, HDIM);

    // 6) softmax -> P fp16 hi
    softmax_convert<<<BATCH * SEQ, 256>>>(S, Ph);

    // 7) out = P . Vt^T + q_seq  (1-pass)
    gemm_mma1<<<dim3(DQ / 128, SEQ / 128, BATCH), 256, SMEM1>>>(
        Ph, SEQ, SEQ, Vth, SEQ, DQ, out, DQ, SEQ, q_seq, SEQ);
}

// round 16
// speedup vs baseline: 1.0588x; 1.0588x over previous
#include <cuda_runtime.h>
#include <cuda_fp16.h>
#include <cstdint>
#include <math_constants.h>

// ============================ problem shapes ============================
#define BATCH 8
#define SEQ   2048
#define DQ    512
#define DKV   768
#define HDIM  512
#define MROWS (BATCH*SEQ)   // 16384

// ============================ device scratch ============================
__device__ __half g_Xh[(size_t)MROWS*DQ],  g_Xl[(size_t)MROWS*DQ];
__device__ __half g_KVh[(size_t)MROWS*DKV], g_KVl[(size_t)MROWS*DKV];
__device__ __half g_Wqh[HDIM*DQ],  g_Wql[HDIM*DQ];
__device__ __half g_Wkh[HDIM*DKV], g_Wkl[HDIM*DKV];
__device__ __half g_Wvh[DQ*DKV];
__device__ float  g_F [(size_t)MROWS*HDIM];
__device__ float  g_F2[(size_t)MROWS*HDIM];
__device__ float  g_F3[(size_t)MROWS*DQ];
__device__ __half g_Qh[(size_t)MROWS*HDIM], g_Ql[(size_t)MROWS*HDIM];
__device__ __half g_Kh[(size_t)MROWS*HDIM], g_Kl[(size_t)MROWS*HDIM];
__device__ __half g_Vth[(size_t)BATCH*DQ*SEQ];
__device__ float  g_S[(size_t)BATCH*SEQ*SEQ];
__device__ __half g_Ph[(size_t)BATCH*SEQ*SEQ];

// ============================ GEMM config (R14 proven engine) ============================
// CTA tile 128x128, K-tile 32 fp16, 3 stages, 128 threads (4 warps: 2m x 2n, 64x64 each).
// 2 CTAs per SM. Tile: 128 rows x 64 B, XOR-swizzled (chunk ^= (row>>1)&3).
#define TILE_B   8192
#define NST      3

__device__ __forceinline__ uint32_t smem_u32(const void* p) {
    uint32_t a;
    asm("{ .reg .u64 t; cvta.to.shared.u64 t, %1; cvt.u32.u64 %0, t; }" : "=r"(a) : "l"(p));
    return a;
}
__device__ __forceinline__ void cp16(uint32_t sa, const void* ga) {
    asm volatile("cp.async.cg.shared.global [%0], [%1], 16;\n" :: "r"(sa), "l"(ga));
}
__device__ __forceinline__ void ldsm_x4(uint32_t* r, uint32_t addr) {
    asm volatile("ldmatrix.sync.aligned.m8n8.x4.shared.b16 {%0,%1,%2,%3}, [%4];"
                 : "=r"(r[0]), "=r"(r[1]), "=r"(r[2]), "=r"(r[3]) : "r"(addr));
}
__device__ __forceinline__ void mma_f16(float* c,
                                        const uint32_t* a, uint32_t b0, uint32_t b1) {
    asm volatile(
        "mma.sync.aligned.m16n8k16.row.col.f32.f16.f16.f32 "
        "{%0,%1,%2,%3}, {%4,%5,%6,%7}, {%8,%9}, {%0,%1,%2,%3};\n"
        : "+f"(c[0]), "+f"(c[1]), "+f"(c[2]), "+f"(c[3])
        : "r"(a[0]), "r"(a[1]), "r"(a[2]), "r"(a[3]), "r"(b0), "r"(b1));
}

// Shared GEMM body. NPASS=3: C = Ah*Bh + Ah*Bl + Al*Bh ; NPASS=1: C = Ah*Bh.
template<int NPASS>
__device__ __forceinline__ void gemm_body(
    const __half* __restrict__ Ah, const __half* __restrict__ Al, int lda, size_t aRow0,
    const __half* __restrict__ Bh, const __half* __restrict__ Bl, int ldb, size_t bRow0,
    float* __restrict__ C, int ldc, size_t cRow0, int n0,
    const float* __restrict__ bias, const float* __restrict__ Res,
    int Ktot, int epi, char* smem)
{
    constexpr int NTILE   = (NPASS == 3) ? 4 : 2;
    constexpr int STAGE_B = NTILE * TILE_B;
    constexpr uint32_t BOFF = (NPASS == 3) ? 2u * TILE_B : (uint32_t)TILE_B;
    constexpr int BH_TILE = (NPASS == 3) ? 2 : 1;

    const uint32_t sb = smem_u32(smem);
    const int tid  = threadIdx.x;
    const int wid  = tid >> 5;
    const int lane = tid & 31;
    const int g    = lane >> 2;
    const int t4   = lane & 3;
    const int wm   = wid & 1;
    const int wn   = wid >> 1;

    const int laneRow = (lane & 7) + ((lane >> 3) & 1) * 8;
    const int hi      = (lane >> 4) & 1;
    const int sw      = (laneRow >> 1) & 3;
    const uint32_t cb0 = (uint32_t)((hi ^ sw) * 16);
    const uint32_t cb1 = (uint32_t)(((2 + hi) ^ sw) * 16);

    float acc[4][8][4];
#pragma unroll
    for (int mt = 0; mt < 4; mt++)
#pragma unroll
        for (int nt = 0; nt < 8; nt++)
#pragma unroll
            for (int r = 0; r < 4; r++) acc[mt][nt][r] = 0.f;

    const int nkb = Ktot >> 5;

    auto load_stage = [&](uint32_t st, int k0) {
#pragma unroll
        for (int j = 0; j < NTILE * 4; j++) {
            const int i = tid + j * 128;
            const int tile = i >> 9;
            const int r = (i >> 2) & 127;
            const int c = i & 3;
            const __half* gp;
            if (tile == 0)                        gp = Ah + (aRow0 + r) * (size_t)lda + k0 + c * 8;
            else if (NPASS == 3 && tile == 1)     gp = Al + (aRow0 + r) * (size_t)lda + k0 + c * 8;
            else if (tile == BH_TILE)             gp = Bh + (bRow0 + r) * (size_t)ldb + k0 + c * 8;
            else                                  gp = Bl + (bRow0 + r) * (size_t)ldb + k0 + c * 8;
            const uint32_t sa = st + tile * TILE_B + r * 64 +
                                ((uint32_t)(c ^ ((r >> 1) & 3)) << 4);
            cp16(sa, gp);
        }
    };

    load_stage(sb, 0);
    asm volatile("cp.async.commit_group;\n" ::: "memory");
    load_stage(sb + STAGE_B, 32);
    asm volatile("cp.async.commit_group;\n" ::: "memory");

    const uint32_t aRowB = (uint32_t)((wm * 64 + laneRow) * 64);
    const uint32_t bRowB = (uint32_t)((wn * 64 + laneRow) * 64);

    int s = 0, sp2 = 2;
    for (int kb = 0; kb < nkb; kb++) {
        asm volatile("cp.async.wait_group 1;\n" ::: "memory");
        __syncthreads();
        if (kb + 2 < nkb)
            load_stage(sb + sp2 * STAGE_B, (kb + 2) << 5);
        asm volatile("cp.async.commit_group;\n" ::: "memory");

        const uint32_t st = sb + s * STAGE_B;
        const uint32_t aBase = st + aRowB;
        const uint32_t bBase = st + BOFF + bRowB;

#pragma unroll
        for (int ks = 0; ks < 2; ks++) {
            const uint32_t cb = ks ? cb1 : cb0;
            uint32_t bh[4][4];
#pragma unroll
            for (int nb = 0; nb < 4; nb++)
                ldsm_x4(bh[nb], bBase + nb * 1024 + cb);
            uint32_t bl[4][4];
            if (NPASS == 3) {
#pragma unroll
                for (int nb = 0; nb < 4; nb++)
                    ldsm_x4(bl[nb], bBase + TILE_B + nb * 1024 + cb);
            }
#pragma unroll
            for (int mt = 0; mt < 4; mt++) {
                uint32_t ah[4], al[4];
                ldsm_x4(ah, aBase + mt * 1024 + cb);
                if (NPASS == 3)
                    ldsm_x4(al, aBase + TILE_B + mt * 1024 + cb);
#pragma unroll
                for (int nt = 0; nt < 8; nt++)
                    mma_f16(acc[mt][nt], ah,
                            bh[nt >> 1][nt & 1], bh[nt >> 1][2 + (nt & 1)]);
                if (NPASS == 3) {
#pragma unroll
                    for (int nt = 0; nt < 8; nt++)
                        mma_f16(acc[mt][nt], ah,
                                bl[nt >> 1][nt & 1], bl[nt >> 1][2 + (nt & 1)]);
#pragma unroll
                    for (int nt = 0; nt < 8; nt++)
                        mma_f16(acc[mt][nt], al,
                                bh[nt >> 1][nt & 1], bh[nt >> 1][2 + (nt & 1)]);
                }
            }
        }
        if (++s == NST) s = 0;
        if (++sp2 == NST) sp2 = 0;
    }

    const int nw0 = n0 + wn * 64;
#pragma unroll
    for (int mt = 0; mt < 4; mt++) {
#pragma unroll
        for (int nt = 0; nt < 8; nt++) {
            const int m = wm * 64 + mt * 16 + g;
            const int n = nw0 + nt * 8 + t4 * 2;
            float v0 = acc[mt][nt][0], v1 = acc[mt][nt][1];
            float v2 = acc[mt][nt][2], v3 = acc[mt][nt][3];
            const size_t i0 = (cRow0 + m) * (size_t)ldc + n;
            const size_t i1 = (cRow0 + m + 8) * (size_t)ldc + n;
            if (epi == 1) {
                const float b0 = bias[n], b1 = bias[n + 1];
                v0 += b0; v1 += b1; v2 += b0; v3 += b1;
            } else if (epi == 2) {
                const float2 r0 = *(const float2*)(Res + i0);
                const float2 r1 = *(const float2*)(Res + i1);
                v0 += r0.x; v1 += r0.y; v2 += r1.x; v3 += r1.y;
            }
            float2 o0; o0.x = v0; o0.y = v1;
            float2 o1; o1.x = v2; o1.y = v3;
            *(float2*)(C + i0) = o0;
            *(float2*)(C + i1) = o1;
        }
    }
}

// Generic batched GEMM wrapper (scores, PV)
template<int NPASS>
__global__ void __launch_bounds__(128, 2) gemm_mma(
    const __half* __restrict__ Ah, const __half* __restrict__ Al, int lda, int aBatch,
    const __half* __restrict__ Bh, const __half* __restrict__ Bl, int ldb, int bBatch,
    float* __restrict__ C, int ldc, int cBatch,
    const float* __restrict__ bias, const float* __restrict__ Res,
    int Ktot, int epi)
{
    extern __shared__ char smem[];
    const size_t aRow0 = (size_t)blockIdx.z * aBatch + (size_t)blockIdx.y * 128;
    const size_t bRow0 = (size_t)blockIdx.z * bBatch + (size_t)blockIdx.x * 128;
    const size_t cRow0 = (size_t)blockIdx.z * cBatch + (size_t)blockIdx.y * 128;
    gemm_body<NPASS>(Ah, Al, lda, aRow0, Bh, Bl, ldb, bRow0,
                     C, ldc, cRow0, blockIdx.x * 128, bias, Res, Ktot, epi, smem);
}

// Fused Q/K/V projection: grid (4, 384)
__global__ void __launch_bounds__(128, 2) gemm_qkv(
    const __half* __restrict__ Xh, const __half* __restrict__ Xl,
    const __half* __restrict__ KVh, const __half* __restrict__ KVl,
    const __half* __restrict__ Wqh, const __half* __restrict__ Wql,
    const __half* __restrict__ Wkh, const __half* __restrict__ Wkl,
    const __half* __restrict__ Wvh,
    const float* __restrict__ bq, const float* __restrict__ bk, const float* __restrict__ bv,
    float* __restrict__ F, float* __restrict__ F2, float* __restrict__ F3)
{
    extern __shared__ char smem[];
    const int part = blockIdx.y >> 7;
    const size_t row0 = (size_t)(blockIdx.y & 127) * 128;
    const size_t bRow0 = (size_t)blockIdx.x * 128;
    const int n0 = blockIdx.x * 128;
    if (part == 0) {
        gemm_body<3>(Xh, Xl, DQ, row0, Wqh, Wql, DQ, bRow0,
                     F, HDIM, row0, n0, bq, nullptr, DQ, 1, smem);
    } else if (part == 1) {
        gemm_body<3>(KVh, KVl, DKV, row0, Wkh, Wkl, DKV, bRow0,
                     F2, HDIM, row0, n0, bk, nullptr, DKV, 1, smem);
    } else {
        gemm_body<1>(KVh, nullptr, DKV, row0, Wvh, nullptr, DKV, bRow0,
                     F3, DQ, row0, n0, bv, nullptr, DKV, 1, smem);
    }
}

// ======================= elementwise / helper kernels =======================
__device__ __forceinline__ void split_h(float x, __half& h, __half& l) {
    h = __float2half_rn(x);
    l = __float2half_rn(x - __half2float(h));
}

__global__ __launch_bounds__(256) void convert_hilo2(
    const float4* __restrict__ inq, __half2* __restrict__ hq, __half2* __restrict__ lq, int n4q,
    const float4* __restrict__ inkv, __half2* __restrict__ hkv, __half2* __restrict__ lkv, int n4kv)
{
    int i = blockIdx.x * 256 + threadIdx.x;
    const float4* in; __half2 *hi, *lo;
    if (i < n4q) { in = inq; hi = hq; lo = lq; }
    else {
        i -= n4q;
        if (i >= n4kv) return;
        in = inkv; hi = hkv; lo = lkv;
    }
    float4 v = in[i];
    __half h0, l0, h1, l1, h2, l2, h3, l3;
    split_h(v.x, h0, l0); split_h(v.y, h1, l1);
    split_h(v.z, h2, l2); split_h(v.w, h3, l3);
    hi[2 * i]     = __halves2half2(h0, h1);
    hi[2 * i + 1] = __halves2half2(h2, h3);
    lo[2 * i]     = __halves2half2(l0, l1);
    lo[2 * i + 1] = __halves2half2(l2, l3);
}

__device__ __forceinline__ void transpose_core(
    const float* __restrict__ in, int ldin,
    __half* __restrict__ oh, __half* __restrict__ ol, int ldout,
    int r0, int c0)
{
    __shared__ float t[32][33];
#pragma unroll
    for (int j = 0; j < 32; j += 8)
        t[threadIdx.y + j][threadIdx.x] =
            in[(size_t)(r0 + threadIdx.y + j) * ldin + c0 + threadIdx.x];
    __syncthreads();
#pragma unroll
    for (int j = 0; j < 32; j += 8) {
        float v = t[threadIdx.x][threadIdx.y + j];
        size_t oidx = (size_t)(c0 + threadIdx.y + j) * ldout + r0 + threadIdx.x;
        if (ol) {
            __half h, l; split_h(v, h, l);
            oh[oidx] = h; ol[oidx] = l;
        } else {
            oh[oidx] = __float2half_rn(v);
        }
    }
}

__global__ void transpose_w(
    const float* __restrict__ Wq, __half* __restrict__ Wqh, __half* __restrict__ Wql,
    const float* __restrict__ Wk, __half* __restrict__ Wkh, __half* __restrict__ Wkl,
    const float* __restrict__ Wv, __half* __restrict__ Wvh)
{
    const int z = blockIdx.z;
    if (z == 0) {
        if (blockIdx.x >= 16) return;
        transpose_core(Wq, HDIM, Wqh, Wql, DQ, blockIdx.x * 32, blockIdx.y * 32);
    } else if (z == 1) {
        transpose_core(Wk, HDIM, Wkh, Wkl, DKV, blockIdx.x * 32, blockIdx.y * 32);
    } else {
        transpose_core(Wv, DQ, Wvh, nullptr, DKV, blockIdx.x * 32, blockIdx.y * 32);
    }
}

__global__ void transpose_v(
    const float* __restrict__ in, __half* __restrict__ oh)
{
    const float* ip = in + (size_t)blockIdx.z * SEQ * DQ;
    __half* op = oh + (size_t)blockIdx.z * DQ * SEQ;
    transpose_core(ip, DQ, op, nullptr, SEQ, blockIdx.x * 32, blockIdx.y * 32);
}

// LayerNorm, 128 threads/row, float4 loads. oh==null -> fp32 in place.
__device__ __forceinline__ void ln_core4(
    float* __restrict__ row, const float* __restrict__ gam, const float* __restrict__ bet,
    __half* __restrict__ oh, __half* __restrict__ ol, size_t obase)
{
    const int tid = threadIdx.x;   // 0..127
    float4 v = *(const float4*)(row + tid * 4);
    __shared__ float sred[4];

    float s = v.x + v.y + v.z + v.w;
#pragma unroll
    for (int o = 16; o; o >>= 1) s += __shfl_xor_sync(0xffffffffu, s, o);
    if ((tid & 31) == 0) sred[tid >> 5] = s;
    __syncthreads();
    const float mean = (sred[0] + sred[1] + sred[2] + sred[3]) * (1.0f / 512.0f);

    const float d0 = v.x - mean, d1 = v.y - mean, d2 = v.z - mean, d3 = v.w - mean;
    float q = d0 * d0 + d1 * d1 + d2 * d2 + d3 * d3;
#pragma unroll
    for (int o = 16; o; o >>= 1) q += __shfl_xor_sync(0xffffffffu, q, o);
    __syncthreads();
    if ((tid & 31) == 0) sred[tid >> 5] = q;
    __syncthreads();
    const float rstd = rsqrtf((sred[0] + sred[1] + sred[2] + sred[3]) * (1.0f / 512.0f) + 1e-5f);

    const float4 gm = *(const float4*)(gam + tid * 4);
    const float4 bt = *(const float4*)(bet + tid * 4);
    float r0 = d0 * rstd * gm.x + bt.x;
    float r1 = d1 * rstd * gm.y + bt.y;
    float r2 = d2 * rstd * gm.z + bt.z;
    float r3 = d3 * rstd * gm.w + bt.w;
    if (oh) {
        __half h0, l0, h1, l1, h2, l2, h3, l3;
        split_h(r0, h0, l0); split_h(r1, h1, l1);
        split_h(r2, h2, l2); split_h(r3, h3, l3);
        __half2* oh2 = (__half2*)(oh + obase + tid * 4);
        __half2* ol2 = (__half2*)(ol + obase + tid * 4);
        oh2[0] = __halves2half2(h0, h1); oh2[1] = __halves2half2(h2, h3);
        ol2[0] = __halves2half2(l0, l1); ol2[1] = __halves2half2(l2, l3);
    } else {
        float4 o; o.x = r0; o.y = r1; o.z = r2; o.w = r3;
        *(float4*)(row + tid * 4) = o;
    }
}

__global__ __launch_bounds__(128) void ln_qkv(
    float* __restrict__ F,  const float* __restrict__ gq, const float* __restrict__ betaq,
    __half* __restrict__ Qh, __half* __restrict__ Ql,
    float* __restrict__ F2, const float* __restrict__ gk, const float* __restrict__ betak,
    __half* __restrict__ Kh, __half* __restrict__ Kl,
    float* __restrict__ F3, const float* __restrict__ gv, const float* __restrict__ betav)
{
    const int b = blockIdx.x;
    if (b < MROWS) {
        ln_core4(F + (size_t)b * 512, gq, betaq, Qh, Ql, (size_t)b * 512);
    } else if (b < 2 * MROWS) {
        const int r = b - MROWS;
        ln_core4(F2 + (size_t)r * 512, gk, betak, Kh, Kl, (size_t)r * 512);
    } else {
        const int r = b - 2 * MROWS;
        ln_core4(F3 + (size_t)r * 512, gv, betav, nullptr, nullptr, 0);
    }
}

// Row softmax over 2048 -> fp16 hi; float4 loads, half2 stores
__global__ __launch_bounds__(256) void softmax_convert(
    const float* __restrict__ S, __half* __restrict__ Ph)
{
    const float4* row = (const float4*)(S + (size_t)blockIdx.x * 2048);
    const int tid = threadIdx.x;
    __shared__ float sred[8];

    float4 a = row[tid];
    float4 b = row[tid + 256];
    float lmax = fmaxf(fmaxf(fmaxf(a.x, a.y), fmaxf(a.z, a.w)),
                       fmaxf(fmaxf(b.x, b.y), fmaxf(b.z, b.w)));
#pragma unroll
    for (int o = 16; o; o >>= 1) lmax = fmaxf(lmax, __shfl_xor_sync(0xffffffffu, lmax, o));
    if ((tid & 31) == 0) sred[tid >> 5] = lmax;
    __syncthreads();
    float m = sred[0];
#pragma unroll
    for (int i = 1; i < 8; i++) m = fmaxf(m, sred[i]);

    a.x = __expf(a.x - m); a.y = __expf(a.y - m); a.z = __expf(a.z - m); a.w = __expf(a.w - m);
    b.x = __expf(b.x - m); b.y = __expf(b.y - m); b.z = __expf(b.z - m); b.w = __expf(b.w - m);
    float lsum = (a.x + a.y) + (a.z + a.w) + (b.x + b.y) + (b.z + b.w);
#pragma unroll
    for (int o = 16; o; o >>= 1) lsum += __shfl_xor_sync(0xffffffffu, lsum, o);
    __syncthreads();
    if ((tid & 31) == 0) sred[tid >> 5] = lsum;
    __syncthreads();
    float tot = 0.f;
#pragma unroll
    for (int i = 0; i < 8; i++) tot += sred[i];
    const float inv = 1.0f / tot;

    __half2* out = (__half2*)(Ph + (size_t)blockIdx.x * 2048);
    out[2 * tid]           = __halves2half2(__float2half_rn(a.x * inv), __float2half_rn(a.y * inv));
    out[2 * tid + 1]       = __halves2half2(__float2half_rn(a.z * inv), __float2half_rn(a.w * inv));
    out[2 * (tid + 256)]     = __halves2half2(__float2half_rn(b.x * inv), __float2half_rn(b.y * inv));
    out[2 * (tid + 256) + 1] = __halves2half2(__float2half_rn(b.z * inv), __float2half_rn(b.w * inv));
}

// ============================ launch ============================
extern "C" void kernel_launch(void* const* d_in, const int* in_sizes, int n_in,
                              void* d_out, int out_size)
{
    const float* q_seq = (const float*)d_in[0];
    const float* kv    = (const float*)d_in[1];
    const float* Wq    = (const float*)d_in[2];
    const float* bq    = (const float*)d_in[3];
    const float* gq    = (const float*)d_in[4];
    const float* betaq = (const float*)d_in[5];
    const float* Wk    = (const float*)d_in[6];
    const float* bk    = (const float*)d_in[7];
    const float* gk    = (const float*)d_in[8];
    const float* betak = (const float*)d_in[9];
    const float* Wv    = (const float*)d_in[10];
    const float* bv    = (const float*)d_in[11];
    const float* gv    = (const float*)d_in[12];
    const float* betav = (const float*)d_in[13];
    float* out = (float*)d_out;

    __half *Xh, *Xl, *KVh, *KVl, *Wqh, *Wql, *Wkh, *Wkl, *Wvh;
    __half *Qh, *Ql, *Kh, *Kl, *Vth, *Ph;
    float *F, *F2, *F3, *S;
    cudaGetSymbolAddress((void**)&Xh, g_Xh);   cudaGetSymbolAddress((void**)&Xl, g_Xl);
    cudaGetSymbolAddress((void**)&KVh, g_KVh); cudaGetSymbolAddress((void**)&KVl, g_KVl);
    cudaGetSymbolAddress((void**)&Wqh, g_Wqh); cudaGetSymbolAddress((void**)&Wql, g_Wql);
    cudaGetSymbolAddress((void**)&Wkh, g_Wkh); cudaGetSymbolAddress((void**)&Wkl, g_Wkl);
    cudaGetSymbolAddress((void**)&Wvh, g_Wvh);
    cudaGetSymbolAddress((void**)&Qh, g_Qh);   cudaGetSymbolAddress((void**)&Ql, g_Ql);
    cudaGetSymbolAddress((void**)&Kh, g_Kh);   cudaGetSymbolAddress((void**)&Kl, g_Kl);
    cudaGetSymbolAddress((void**)&Vth, g_Vth);
    cudaGetSymbolAddress((void**)&Ph, g_Ph);
    cudaGetSymbolAddress((void**)&F, g_F);     cudaGetSymbolAddress((void**)&F2, g_F2);
    cudaGetSymbolAddress((void**)&F3, g_F3);   cudaGetSymbolAddress((void**)&S, g_S);

    const int SMEM3 = NST * 4 * TILE_B;   // 98304  -> 2 CTAs/SM
    const int SMEM1 = NST * 2 * TILE_B;   // 49152
    cudaFuncSetAttribute((const void*)gemm_qkv, cudaFuncAttributeMaxDynamicSharedMemorySize, SMEM3);
    cudaFuncSetAttribute((const void*)gemm_mma<3>, cudaFuncAttributeMaxDynamicSharedMemorySize, SMEM3);
    cudaFuncSetAttribute((const void*)gemm_mma<1>, cudaFuncAttributeMaxDynamicSharedMemorySize, SMEM1);

    const dim3 tb(32, 8);
    const int n4q = MROWS * DQ / 4, n4kv = MROWS * DKV / 4;

    // 0) split both inputs into fp16 hi/lo
    convert_hilo2<<<(n4q + n4kv + 255) / 256, 256>>>(
        (const float4*)q_seq, (__half2*)Xh, (__half2*)Xl, n4q,
        (const float4*)kv, (__half2*)KVh, (__half2*)KVl, n4kv);

    // 1) transpose all weights
    transpose_w<<<dim3(24, 16, 3), tb>>>(Wq, Wqh, Wql, Wk, Wkh, Wkl, Wv, Wvh);

    // 2) fused Q/K/V projections
    gemm_qkv<<<dim3(4, 384, 1), 128, SMEM3>>>(
        Xh, Xl, KVh, KVl, Wqh, Wql, Wkh, Wkl, Wvh, bq, bk, bv, F, F2, F3);

    // 3) fused LayerNorms (128 thr/row, float4)
    ln_qkv<<<3 * MROWS, 128>>>(F, gq, betaq, Qh, Ql,
                               F2, gk, betak, Kh, Kl,
                               F3, gv, betav);

    // 4) transpose V -> Vt hi [b*512+c, 2048]
    transpose_v<<<dim3(SEQ / 32, DQ / 32, BATCH), tb>>>(F3, Vth);

    // 5) scores S = K . Q^T  (3-pass)
    gemm_mma<3><<<dim3(SEQ / 128, SEQ / 128, BATCH), 128, SMEM3>>>(
        Kh, Kl, HDIM, SEQ, Qh, Ql, HDIM, SEQ, S, SEQ, SEQ, nullptr, nullptr, HDIM, 0);

    // 6) softmax -> P fp16 hi
    softmax_convert<<<BATCH * SEQ, 256>>>(S, Ph);

    // 7) out = P . Vt^T + q_seq  (1-pass)
    gemm_mma<1><<<dim3(DQ / 128, SEQ / 128, BATCH), 128, SMEM1>>>(
        Ph, nullptr, SEQ, SEQ, Vth, nullptr, SEQ, DQ, out, DQ, SEQ, nullptr, q_seq, SEQ, 2);
}